// round 10
// baseline (speedup 1.0000x reference)
#include <cuda_runtime.h>
#include <cstdint>
#include <cstddef>

// Monarch embedding, analytically folded:
//   out[tok][kr*32+o] = (kr&1 == s) ? L[v*16 + kr/2] * R[(kr*32 + c)*32 + o] : 0
//   v = x[tok], k = v/786, s = k>>5, c = k&31.
//
// R10: token binning to make R register-resident.
// Observation: in all prior variants L1% + L2% == 100% -> store path is
// backpressure-serialized; elapsed = T_L1 + T_L2. The only reducible term is
// the 64MiB of logical R re-reads through l1tex (~3.7us). Binning tokens by
// k fixes (c, s) per CTA -> each thread's R float4 (parity pre-folded) loads
// ONCE into registers; inner loop = bin-entry read + L scalar + 4 FMUL + STG.
//   K0: zero 64 bin cursors.
//   K1: scatter (tok, v) into 64 bins via global atomicAdd (order per replay
//       nondeterministic; output invariant).
//   K2: 64 bins x 16 sub-CTAs, 256 thr; CTA writes full 4KB rows; depth-2
//       rolling prefetch on the bins->L dependent chain.

#define NBIN 64
#define BCAP 1024                 // mean 256/bin, sd ~16 -> 1024 is >16 sigma
#define SUBS 16                   // sub-CTAs per bin

__device__ int  g_cursor[NBIN];
__device__ int2 g_bins[NBIN * BCAP];

__global__ void zero_cursors_kernel() {
    g_cursor[threadIdx.x] = 0;
}

__global__ void __launch_bounds__(256) bin_tokens_kernel(const int* __restrict__ x) {
    const int t0 = (blockIdx.x * 256 + threadIdx.x) << 2;
    const int4 xv = *reinterpret_cast<const int4*>(x + t0);
    const int vs[4] = {xv.x, xv.y, xv.z, xv.w};
#pragma unroll
    for (int t = 0; t < 4; t++) {
        const int v = vs[t];
        const int k = v / 786;                       // bin id 0..63
        const int pos = atomicAdd(&g_cursor[k], 1);
        g_bins[k * BCAP + pos] = make_int2(t0 + t, v);
    }
}

__global__ void __launch_bounds__(256) scatter_rows_kernel(
    const float* __restrict__ L,
    const float* __restrict__ R,
    float* __restrict__ out)
{
    const int bin = blockIdx.x >> 4;       // 0..63
    const int sub = blockIdx.x & (SUBS - 1);
    const int cnt = g_cursor[bin];         // uniform broadcast load
    const int s   = bin >> 5;
    const int c   = bin & 31;

    const int tid = threadIdx.x;
    const int kr  = tid >> 3;              // 0..31
    const int o   = (tid & 7) << 2;        // 0..28
    const int i   = kr >> 1;               // L column 0..15
    const int p   = kr & 1;                // row parity

    // R value for this thread, loaded ONCE; parity mask pre-folded.
    float4 re = *reinterpret_cast<const float4*>(
        &R[((size_t)((kr << 5) + c) << 5) + o]);
    if (s != p) re = make_float4(0.f, 0.f, 0.f, 0.f);

    const int2* bp = g_bins + bin * BCAP;

    // Depth-2 rolling pipeline over this sub-CTA's tokens (stride SUBS).
    int  ic = sub;                          // current
    int  in = sub + SUBS;                   // next
    int2 tc = (ic < cnt) ? bp[ic] : make_int2(0, 0);
    int2 tn = (in < cnt) ? bp[in] : make_int2(0, 0);
    float lc = __ldg(&L[(size_t)tc.y * 16 + i]);

    while (ic < cnt) {
        const int inn = in + SUBS;
        int2 tnn = (inn < cnt) ? bp[inn] : make_int2(0, 0);
        const float ln = __ldg(&L[(size_t)tn.y * 16 + i]);

        // Store current token's full row slice (CTA covers the 4KB row).
        *reinterpret_cast<float4*>(&out[(size_t)tc.x * 1024 + (tid << 2)]) =
            make_float4(lc * re.x, lc * re.y, lc * re.z, lc * re.w);

        ic = in; in = inn;
        tc = tn; tn = tnn;
        lc = ln;
    }
}

extern "C" void kernel_launch(void* const* d_in, const int* in_sizes, int n_in,
                              void* d_out, int out_size) {
    const int*   x = (const int*)  d_in[0];   // (8, 2048) int32
    const float* L = (const float*)d_in[1];   // (64, 786, 16) f32
    const float* R = (const float*)d_in[2];   // (32, 32, 32) f32
    // d_in[3] = p : analytically folded (perfect_shuffle(64, 1024))

    zero_cursors_kernel<<<1, NBIN>>>();
    bin_tokens_kernel<<<16, 256>>>(x);                      // 16384 tokens
    scatter_rows_kernel<<<NBIN * SUBS, 256>>>(L, R, (float*)d_out);
}

// round 11
// speedup vs baseline: 1.5619x; 1.5619x over previous
#include <cuda_runtime.h>
#include <cstdint>
#include <cstddef>

// Monarch embedding, analytically folded:
//   out[tok][kr*32+o] = (kr&1 == s) ? L[v*16 + kr/2] * R[(kr*32 + c)*32 + o] : 0
//   v = x[tok], k = v/786, s = k>>5, c = k&31.
//
// R11 = R9 (256-bit ld/st, fewest instructions) + parity-pure warps so the
// zero half of the output costs ONLY its stores: zero warps skip the R v8
// load and the L gather via a warp-uniform branch. Store stream (64MiB) is
// the floor (~2500-3000 B/cyc LTS store path); this trims the L1 read
// traffic that serializes against it.
//
// Map: 256 thr, th = tid>>7 (token of pair), slot = tid&127,
//   u = slot>>5 (warp-in-half), l = slot&31, p = u&1 (warp parity),
//   kr = ((u>>1)<<4) + ((l>>2)<<1) + p   (8 same-parity rows per warp),
//   osub = (l&3)*8, i = kr>>1.
// Coverage per token-half: 4 warps x 8 rows x 32B = full 4KB row.

__global__ void __launch_bounds__(256) monarch_embed_kernel(
    const int* __restrict__ x,
    const float* __restrict__ L,
    const float* __restrict__ R,
    float* __restrict__ out)
{
    const int tb   = blockIdx.x << 2;      // 4 tokens per CTA
    const int tid  = threadIdx.x;
    const int th   = tid >> 7;             // 0/1: token of each pair
    const int slot = tid & 127;
    const int u    = slot >> 5;            // warp within token-half
    const int l    = slot & 31;
    const int p    = u & 1;                // warp parity (uniform!)
    const int kr   = ((u >> 1) << 4) + ((l >> 2) << 1) + p;   // 0..31
    const int osub = (l & 3) << 3;         // 0,8,16,24
    const int i    = kr >> 1;              // L column 0..15

    // One aligned 128-bit load covers x for all 4 tokens.
    const int4 xv = *reinterpret_cast<const int4*>(x + tb);
    const int v0 = th ? xv.y : xv.x;       // pass-0 token
    const int v1 = th ? xv.w : xv.z;       // pass-1 token

    const int k0 = v0 / 786, s0 = k0 >> 5, c0 = k0 & 31;
    const int k1 = v1 / 786, s1 = k1 >> 5, c1 = k1 & 31;

    // Fire long-latency L gathers early, only for active tokens (warp-uniform).
    float lva = 0.0f, lvb = 0.0f;
    if (s0 == p) lva = __ldg(&L[(size_t)v0 * 16 + i]);
    if (s1 == p) lvb = __ldg(&L[(size_t)v1 * 16 + i]);

    float* ob = out + (size_t)(tb + th) * 1024 + (kr << 5) + osub;

#pragma unroll
    for (int m = 0; m < 2; m++) {
        const int   act = m ? (s1 == p) : (s0 == p);   // warp-uniform
        const int   c   = m ? c1  : c0;
        const float lvf = m ? lvb : lva;
        float* op = ob + (size_t)m * 2048;             // pass-1 token = tb+2+th

        if (act) {
            const float* rp = &R[((size_t)((kr << 5) + c) << 5) + osub];
            float r0, r1, r2, r3, r4, r5, r6, r7;
            asm("ld.global.v8.f32 {%0,%1,%2,%3,%4,%5,%6,%7}, [%8];"
                : "=f"(r0), "=f"(r1), "=f"(r2), "=f"(r3),
                  "=f"(r4), "=f"(r5), "=f"(r6), "=f"(r7)
                : "l"(rp));
            r0 *= lvf; r1 *= lvf; r2 *= lvf; r3 *= lvf;
            r4 *= lvf; r5 *= lvf; r6 *= lvf; r7 *= lvf;
            asm volatile("st.global.v8.f32 [%0], {%1,%2,%3,%4,%5,%6,%7,%8};"
                :: "l"(op),
                   "f"(r0), "f"(r1), "f"(r2), "f"(r3),
                   "f"(r4), "f"(r5), "f"(r6), "f"(r7)
                : "memory");
        } else {
            const float z = 0.0f;
            asm volatile("st.global.v8.f32 [%0], {%1,%1,%1,%1,%1,%1,%1,%1};"
                :: "l"(op), "f"(z) : "memory");
        }
    }
}

extern "C" void kernel_launch(void* const* d_in, const int* in_sizes, int n_in,
                              void* d_out, int out_size) {
    const int*   x = (const int*)  d_in[0];   // (8, 2048) int32
    const float* L = (const float*)d_in[1];   // (64, 786, 16) f32
    const float* R = (const float*)d_in[2];   // (32, 32, 32) f32
    // d_in[3] = p : analytically folded (perfect_shuffle(64, 1024))

    const int ntok = out_size / 1024;         // 16384 tokens
    monarch_embed_kernel<<<ntok / 4, 256>>>(x, L, R, (float*)d_out);
}